// round 8
// baseline (speedup 1.0000x reference)
#include <cuda_runtime.h>
#include <cstdint>

// OrderParameter: C=30000 centrals, K=32 neighbors. One warp per central.
// Fast path (mask all-ones): symmetric-pair loop, offsets o=1..16, lane j pairs
// with (j+o) mod 32; offsets packed (o, o+8) in f32x2 through dot/acos chain.
// r-space: r = acos(|c|);  gt (theta>160deg, c<0): (theta-pi)^2 = r^2;
// (theta-pi/2)^2 = (r-pi/2)^2 any sign; lt tetra center theta0 / pi-theta0.
// Merged exp serves tetra-gaussian (lt) or term1 (gt); gt tetra tail <=2.8e-6
// dropped (~1e-5 in G).
//
// R8 change: __launch_bounds__(256, 4) -> 64-reg budget so the packed poly
// constants and accumulators stay register-resident (kills per-step
// rematerialization MOVs seen as the ~300-instruction gap vs model).
//
//   q_tet   = 1 - 3*S/(n(n-1))
//   q_tetra = G/(n(n-1))
//   q_oct   = [2*T1 + sum_rows e2s_j*(row_lt_j-1)] / (n*(3+(n-2)(n-3)))
//
// row_lt/e2s packed per row: val = 2.25*e2 + 256 (lt) or 0 (gt); v <= 8006,
// cnt = floor(v/256 + 0.03) exact.

#define FULLMASK 0xffffffffu

__device__ __forceinline__ float ex2f(float x) {
    float r; asm("ex2.approx.f32 %0, %1;" : "=f"(r) : "f"(x)); return r;
}
__device__ __forceinline__ float sqrt_ap(float x) {
    float r; asm("sqrt.approx.f32 %0, %1;" : "=f"(r) : "f"(x)); return r;
}

// ---- f32x2 packed helpers ----
__device__ __forceinline__ uint64_t pk2(float lo, float hi) {
    uint64_t d; asm("mov.b64 %0, {%1, %2};" : "=l"(d) : "f"(lo), "f"(hi)); return d;
}
__device__ __forceinline__ void upk2(uint64_t d, float& lo, float& hi) {
    asm("mov.b64 {%0, %1}, %2;" : "=f"(lo), "=f"(hi) : "l"(d));
}
__device__ __forceinline__ uint64_t bc2(float v) { return pk2(v, v); }
__device__ __forceinline__ uint64_t f2mul(uint64_t a, uint64_t b) {
    uint64_t d; asm("mul.rn.f32x2 %0, %1, %2;" : "=l"(d) : "l"(a), "l"(b)); return d;
}
__device__ __forceinline__ uint64_t f2add(uint64_t a, uint64_t b) {
    uint64_t d; asm("add.rn.f32x2 %0, %1, %2;" : "=l"(d) : "l"(a), "l"(b)); return d;
}
__device__ __forceinline__ uint64_t f2fma(uint64_t a, uint64_t b, uint64_t c) {
    uint64_t d; asm("fma.rn.f32x2 %0, %1, %2, %3;" : "=l"(d) : "l"(a), "l"(b), "l"(c)); return d;
}

// ---- constants ----
#define PI_F      3.14159265358979323846f
#define HALF_PI_F 1.57079632679489661923f
#define THETA0_F  1.91061193216957395f     // 109.47 deg
#define PMT0_F    1.23098072142021928f     // pi - theta0
#define THR_F     2.79252680319092716f     // 160 deg
#define COS_THR_F (-0.93969262078590838f)  // cos(160 deg)
#define LOG2E_F   1.44269504088896340f
#define D_LT_F    0.17453292519943295f     // 10 deg
#define D1_F      0.20943951023931953f     // 12 deg
#define KG_F  (-LOG2E_F / (2.0f * D_LT_F * D_LT_F))   // 10-deg widths
#define K1_F  (-LOG2E_F / (2.0f * D1_F  * D1_F ))     // term1 (12 deg)

// Packed acos-poly constants, passed in (register-resident with 64-reg budget).
struct PolyC {
    uint64_t k7, k6, k5, k4, k3, k2, k1, k0, third, none;
};

// Scalar r-space tail for one pair. WH2: 2*weight (2 or 1).
template<int WH2>
__device__ __forceinline__ float tail_r(float r, float c, float& g, float& t1)
{
    const float wsym = 0.5f * (float)WH2;
    const bool gt = c < COS_THR_F;                  // theta > 160 deg
    const float ctr = gt ? 0.0f : ((c >= 0.0f) ? THETA0_F : PMT0_F);
    const float kk  = gt ? K1_F : KG_F;
    const float d1  = r - ctr;
    const float e1  = ex2f((kk * d1) * d1);
    g  = fmaf(gt ? 0.0f : wsym,        e1, g);
    t1 = fmaf(gt ? 3.0f * wsym : 0.0f, e1, t1);
    const float d2 = r - HALF_PI_F;
    const float e2 = ex2f((KG_F * d2) * d2);
    return gt ? 0.0f : fmaf(2.25f, e2, 256.0f);
}

template<int O0, int O1, bool LAST>
__device__ __forceinline__ void pair_step(
    uint64_t x2, uint64_t y2, uint64_t z2,
    float x, float y, float z, int lane, const PolyC& P,
    uint64_t& s2, float& g, float& t1, float& vo, float& vm)
{
    // modulo-wrap shuffles (srcLane % 32 semantics)
    const float xl = __shfl_sync(FULLMASK, x, lane + O0);
    const float yl = __shfl_sync(FULLMASK, y, lane + O0);
    const float zl = __shfl_sync(FULLMASK, z, lane + O0);
    const float xh = __shfl_sync(FULLMASK, x, lane + O1);
    const float yh = __shfl_sync(FULLMASK, y, lane + O1);
    const float zh = __shfl_sync(FULLMASK, z, lane + O1);

    const uint64_t c2 = f2fma(x2, pk2(xl, xh),
                        f2fma(y2, pk2(yl, yh), f2mul(z2, pk2(zl, zh))));

    // q_tet: (c + 1/3)^2, hi half-weight on last step
    const uint64_t a2  = f2add(c2, P.third);
    const uint64_t aa2 = f2mul(a2, a2);
    s2 = LAST ? f2fma(aa2, pk2(1.0f, 0.5f), s2) : f2add(aa2, s2);

    // packed r = acos(|c|) via A&S 4.4.46: sqrt(1-|c|)*poly(|c|)
    const uint64_t t2 = c2 & 0x7FFFFFFF7FFFFFFFull;
    uint64_t p2 = P.k7;
    p2 = f2fma(p2, t2, P.k6);
    p2 = f2fma(p2, t2, P.k5);
    p2 = f2fma(p2, t2, P.k4);
    p2 = f2fma(p2, t2, P.k3);
    p2 = f2fma(p2, t2, P.k2);
    p2 = f2fma(p2, t2, P.k1);
    p2 = f2fma(p2, t2, P.k0);
    const uint64_t om2 = f2fma(t2, P.none, bc2(1.0f));   // 1-|c| >= -2e-7
    float omlo, omhi; upk2(om2, omlo, omhi);
    const uint64_t sq2 = pk2(sqrt_ap(fmaxf(omlo, 0.0f)), sqrt_ap(fmaxf(omhi, 0.0f)));
    const uint64_t r2 = f2mul(sq2, p2);                  // r = acos(|c|)

    float rlo, rhi; upk2(r2, rlo, rhi);
    float clo, chi; upk2(c2, clo, chi);

    const float vlo = tail_r<2>(rlo, clo, g, t1);
    const float vhi = LAST ? tail_r<1>(rhi, chi, g, t1)
                           : tail_r<2>(rhi, chi, g, t1);

    vo += vlo + vhi;
    vm += __shfl_sync(FULLMASK, vlo, lane + (32 - O0));
    const float mh = __shfl_sync(FULLMASK, vhi, lane + (32 - O1));
    if (!LAST) vm += mh;
}

__global__ __launch_bounds__(256, 4) void order_param_kernel(
    const float* __restrict__ vecs,  // [C, 32, 3]
    const int*   __restrict__ mask,  // [C, 32] int32 0/1
    float* __restrict__ out,         // [3, C]
    int C)
{
    const int warp_global = (blockIdx.x * blockDim.x + threadIdx.x) >> 5;
    const int lane = threadIdx.x & 31;
    if (warp_global >= C) return;

    const float* vp = vecs + (size_t)warp_global * 96 + lane * 3;
    const bool valid = mask[(size_t)warp_global * 32 + lane] != 0;
    float x = 0.0f, y = 0.0f, z = 1.0f;
    if (valid) { x = vp[0]; y = vp[1]; z = vp[2]; }
    const float inv = rsqrtf(fmaf(x, x, fmaf(y, y, z * z)));
    x *= inv; y *= inv; z *= inv;

    const unsigned mm = __ballot_sync(FULLMASK, valid);

    float S, G, O;

    if (mm == FULLMASK) {
        // ---------- fast path: all 32 neighbors valid ----------
        const uint64_t x2 = bc2(x), y2 = bc2(y), z2 = bc2(z);
        uint64_t s2 = 0;
        float g = 0.0f, t1 = 0.0f, vo = 0.0f, vm = 0.0f;

        PolyC P;
        P.k7 = bc2(-0.0012624911f);
        P.k6 = bc2( 0.0066700901f);
        P.k5 = bc2(-0.0170881256f);
        P.k4 = bc2( 0.0308918810f);
        P.k3 = bc2(-0.0501743046f);
        P.k2 = bc2( 0.0889789874f);
        P.k1 = bc2(-0.2145988016f);
        P.k0 = bc2( 1.5707963050f);
        P.third = bc2(1.0f / 3.0f);
        P.none  = bc2(-1.0f);

        pair_step<1, 9,  false>(x2, y2, z2, x, y, z, lane, P, s2, g, t1, vo, vm);
        pair_step<2, 10, false>(x2, y2, z2, x, y, z, lane, P, s2, g, t1, vo, vm);
        pair_step<3, 11, false>(x2, y2, z2, x, y, z, lane, P, s2, g, t1, vo, vm);
        pair_step<4, 12, false>(x2, y2, z2, x, y, z, lane, P, s2, g, t1, vo, vm);
        pair_step<5, 13, false>(x2, y2, z2, x, y, z, lane, P, s2, g, t1, vo, vm);
        pair_step<6, 14, false>(x2, y2, z2, x, y, z, lane, P, s2, g, t1, vo, vm);
        pair_step<7, 15, false>(x2, y2, z2, x, y, z, lane, P, s2, g, t1, vo, vm);
        pair_step<8, 16, true >(x2, y2, z2, x, y, z, lane, P, s2, g, t1, vo, vm);

        float slo, shi; upk2(s2, slo, shi);
        S = 2.0f * (slo + shi);
        G = 2.0f * g;
        const float v   = vo + vm;                          // e2s + 256*row_lt
        const float cnt = floorf(fmaf(v, 1.0f / 256.0f, 0.03f));
        const float e2s = fmaf(-256.0f, cnt, v);
        O = fmaf(e2s, cnt - 1.0f, 2.0f * t1);
    } else {
        // ---------- generic path (verified R3 loop) ----------
        const float NEG_I2DLT2 = -1.0f / (2.0f * D_LT_F * D_LT_F);
        const float NEG_I2D12  = -1.0f / (2.0f * D1_F * D1_F);

        float s_acc = 0.0f, g_acc = 0.0f, t1_acc = 0.0f, e2s = 0.0f;
        int row_lt = 0;
        #pragma unroll
        for (int o = 1; o <= 16; o++) {
            const int p = (lane + o) & 31;
            const float vx = __shfl_sync(FULLMASK, x, p);
            const float vy = __shfl_sync(FULLMASK, y, p);
            const float vz = __shfl_sync(FULLMASK, z, p);
            const bool pv = valid && ((mm >> p) & 1u);
            const float w = pv ? 1.0f : 0.0f;

            float c = fmaf(x, vx, fmaf(y, vy, z * vz));
            c = fminf(1.0f, fmaxf(-1.0f, c));
            const float th = acosf(c);

            const float a = c + (1.0f / 3.0f);
            const float s_p = w * a * a;
            const float d0 = th - THETA0_F;
            const float g_p = w * __expf(d0 * d0 * NEG_I2DLT2);
            const float dpi = th - PI_F;
            const float t1_p = (th > THR_F) ? (3.0f * w * __expf(dpi * dpi * NEG_I2D12)) : 0.0f;
            const bool lt = pv && (th < THR_F);
            const float dh = th - HALF_PI_F;
            const float e2_p = lt ? (2.25f * __expf(dh * dh * NEG_I2DLT2)) : 0.0f;
            const unsigned ltm = __ballot_sync(FULLMASK, lt);

            if (o < 16) {
                s_acc += s_p; g_acc += g_p; t1_acc += t1_p;
                const int q = (lane - o) & 31;
                e2s += e2_p + __shfl_sync(FULLMASK, e2_p, q);
                row_lt += (int)((ltm >> lane) & 1u) + (int)((ltm >> q) & 1u);
            } else {
                s_acc  = fmaf(0.5f, s_p,  s_acc);
                g_acc  = fmaf(0.5f, g_p,  g_acc);
                t1_acc = fmaf(0.5f, t1_p, t1_acc);
                e2s += e2_p;
                row_lt += (int)((ltm >> lane) & 1u);
            }
        }
        S = 2.0f * s_acc;
        G = 2.0f * g_acc;
        O = fmaf(e2s, (float)(row_lt - 1), 2.0f * t1_acc);
    }

    #pragma unroll
    for (int off = 16; off > 0; off >>= 1) {
        S += __shfl_xor_sync(FULLMASK, S, off);
        G += __shfl_xor_sync(FULLMASK, G, off);
        O += __shfl_xor_sync(FULLMASK, O, off);
    }

    if (lane == 0) {
        const float n   = (float)__popc(mm);
        const float nn1 = n * (n - 1.0f);
        out[warp_global]         = 1.0f - 3.0f * S / nn1;
        out[C + warp_global]     = G / nn1;
        out[2 * C + warp_global] = O / (n * (3.0f + (n - 2.0f) * (n - 3.0f)));
    }
}

extern "C" void kernel_launch(void* const* d_in, const int* in_sizes, int n_in,
                              void* d_out, int out_size) {
    const float* vecs = (const float*)d_in[0];
    const int*   mask = (const int*)d_in[1];
    float* out = (float*)d_out;
    const int C = in_sizes[0] / (32 * 3);

    const int warps_per_block = 8;   // 256 threads
    const int blocks = (C + warps_per_block - 1) / warps_per_block;
    order_param_kernel<<<blocks, 256>>>(vecs, mask, out, C);
}

// round 9
// speedup vs baseline: 1.0801x; 1.0801x over previous
#include <cuda_runtime.h>
#include <cstdint>

// OrderParameter: C=30000 centrals, K=32 neighbors. One warp per central.
// R9: scalar per-pair math (f32x2 packing measured neutral across R5-R8);
// partner vectors broadcast via duplicated SMEM ring (1 LDS.128 replaces
// 3 SHFLs; immediate offsets, no address math). r-space tail as verified
// in R7/R8 (rel_err 3.6e-6).
//
//   q_tet   = 1 - 3*S/(n(n-1)),  S = sum_ordered (c+1/3)^2 expanded as
//             sum c^2 + 2/3 sum c + count/9
//   q_tetra = G/(n(n-1))
//   q_oct   = [2*T1 + sum_rows e2s_j*(row_lt_j-1)] / (n*(3+(n-2)(n-3)))
//
// row_lt/e2s packed per row: val = 2.25*e2 + 256 (lt) or 0 (gt); v <= 8006,
// cnt = floor(v/256 + 0.03) exact.

#define FULLMASK 0xffffffffu

__device__ __forceinline__ float ex2f(float x) {
    float r; asm("ex2.approx.f32 %0, %1;" : "=f"(r) : "f"(x)); return r;
}
__device__ __forceinline__ float sqrt_ap(float x) {
    float r; asm("sqrt.approx.f32 %0, %1;" : "=f"(r) : "f"(x)); return r;
}

// ---- constants ----
#define PI_F      3.14159265358979323846f
#define HALF_PI_F 1.57079632679489661923f
#define THETA0_F  1.91061193216957395f     // 109.47 deg
#define PMT0_F    1.23098072142021928f     // pi - theta0
#define THR_F     2.79252680319092716f     // 160 deg
#define COS_THR_F (-0.93969262078590838f)  // cos(160 deg)
#define LOG2E_F   1.44269504088896340f
#define D_LT_F    0.17453292519943295f     // 10 deg
#define D1_F      0.20943951023931953f     // 12 deg
#define KG_F  (-LOG2E_F / (2.0f * D_LT_F * D_LT_F))   // 10-deg widths
#define K1_F  (-LOG2E_F / (2.0f * D1_F  * D1_F ))     // term1 (12 deg)

// scalar acos(|c|) then r-space tail; A&S 4.4.46 poly (|err|<=2e-8 rad)
__device__ __forceinline__ float acos_abs(float c) {
    const float t = fabsf(c);
    float p = fmaf(-0.0012624911f, t, 0.0066700901f);
    p = fmaf(p, t, -0.0170881256f);
    p = fmaf(p, t,  0.0308918810f);
    p = fmaf(p, t, -0.0501743046f);
    p = fmaf(p, t,  0.0889789874f);
    p = fmaf(p, t, -0.2145988016f);
    p = fmaf(p, t,  1.5707963050f);
    return sqrt_ap(__saturatef(1.0f - t)) * p;   // FADD.SAT folds the clamp
}

__global__ __launch_bounds__(256) void order_param_kernel(
    const float* __restrict__ vecs,  // [C, 32, 3]
    const int*   __restrict__ mask,  // [C, 32] int32 0/1
    float* __restrict__ out,         // [3, C]
    int C)
{
    __shared__ float4 sv[8][64];     // per-warp normalized vectors, duplicated

    const int tid  = threadIdx.x;
    const int w    = tid >> 5;
    const int lane = tid & 31;
    const int warp_global = blockIdx.x * 8 + w;
    if (warp_global >= C) return;

    const float* vp = vecs + (size_t)warp_global * 96 + lane * 3;
    const bool valid = mask[(size_t)warp_global * 32 + lane] != 0;
    float x = 0.0f, y = 0.0f, z = 1.0f;
    if (valid) { x = vp[0]; y = vp[1]; z = vp[2]; }
    const float inv = rsqrtf(fmaf(x, x, fmaf(y, y, z * z)));
    x *= inv; y *= inv; z *= inv;

    const unsigned mm = __ballot_sync(FULLMASK, valid);

    float S, G, O;

    if (mm == FULLMASK) {
        // ---------- fast path: all 32 neighbors valid ----------
        const float4 me = make_float4(x, y, z, 0.0f);
        sv[w][lane]      = me;
        sv[w][lane + 32] = me;
        __syncwarp();

        const float4* __restrict__ base = &sv[w][lane];

        float a2 = 0.0f, a1 = 0.0f;          // sum c^2, sum c (unordered, o16 half)
        float g = 0.0f, t1 = 0.0f;           // tetra gauss, term1 (unordered)
        float vo = 0.0f, vm = 0.0f;          // own/mirror row packed vals

        #pragma unroll
        for (int o = 1; o <= 15; o++) {
            const float4 pv = base[o];       // LDS.128, immediate offset
            const float c = fmaf(x, pv.x, fmaf(y, pv.y, z * pv.z));
            a2 = fmaf(c, c, a2);
            a1 += c;

            const float r = acos_abs(c);     // acos(|c|)
            const bool gt = c < COS_THR_F;   // theta > 160 deg
            const float ctr = gt ? 0.0f : ((c >= 0.0f) ? THETA0_F : PMT0_F);
            const float kk  = gt ? K1_F : KG_F;
            const float d1  = r - ctr;
            const float e1  = ex2f((kk * d1) * d1);
            g  += gt ? 0.0f : e1;
            t1  = fmaf(gt ? 3.0f : 0.0f, e1, t1);

            const float d2 = r - HALF_PI_F;
            const float e2 = ex2f((KG_F * d2) * d2);
            const float val = gt ? 0.0f : fmaf(2.25f, e2, 256.0f);
            vo += val;
            vm += __shfl_sync(FULLMASK, val, lane + (32 - o));  // mirror row
        }
        {   // o = 16: pair computed by both endpoints -> half-weight symmetric,
            // own-only row accumulation (ordered (j, j+16) once)
            const float4 pv = base[16];
            const float c = fmaf(x, pv.x, fmaf(y, pv.y, z * pv.z));
            a2 = fmaf(0.5f * c, c, a2);
            a1 = fmaf(0.5f, c, a1);

            const float r = acos_abs(c);
            const bool gt = c < COS_THR_F;
            const float ctr = gt ? 0.0f : ((c >= 0.0f) ? THETA0_F : PMT0_F);
            const float kk  = gt ? K1_F : KG_F;
            const float d1  = r - ctr;
            const float e1  = ex2f((kk * d1) * d1);
            g  = fmaf(gt ? 0.0f : 0.5f, e1, g);
            t1 = fmaf(gt ? 1.5f : 0.0f, e1, t1);

            const float d2 = r - HALF_PI_F;
            const float e2 = ex2f((KG_F * d2) * d2);
            const float val = gt ? 0.0f : fmaf(2.25f, e2, 256.0f);
            vo += val;
        }

        // per-lane partials; identities hold after the warp reduction
        S = 2.0f * fmaf(2.0f / 3.0f, a1, a2) + 31.0f / 9.0f;
        G = 2.0f * g;
        const float v   = vo + vm;                      // e2s + 256*row_lt
        const float cnt = floorf(fmaf(v, 1.0f / 256.0f, 0.03f));
        const float e2s = fmaf(-256.0f, cnt, v);
        O = fmaf(e2s, cnt - 1.0f, 2.0f * t1);
    } else {
        // ---------- generic path (verified R3 loop) ----------
        const float NEG_I2DLT2 = -1.0f / (2.0f * D_LT_F * D_LT_F);
        const float NEG_I2D12  = -1.0f / (2.0f * D1_F * D1_F);

        float s_acc = 0.0f, g_acc = 0.0f, t1_acc = 0.0f, e2s = 0.0f;
        int row_lt = 0;
        #pragma unroll
        for (int o = 1; o <= 16; o++) {
            const int p = (lane + o) & 31;
            const float vx = __shfl_sync(FULLMASK, x, p);
            const float vy = __shfl_sync(FULLMASK, y, p);
            const float vz = __shfl_sync(FULLMASK, z, p);
            const bool pv = valid && ((mm >> p) & 1u);
            const float wv = pv ? 1.0f : 0.0f;

            float c = fmaf(x, vx, fmaf(y, vy, z * vz));
            c = fminf(1.0f, fmaxf(-1.0f, c));
            const float th = acosf(c);

            const float a = c + (1.0f / 3.0f);
            const float s_p = wv * a * a;
            const float d0 = th - THETA0_F;
            const float g_p = wv * __expf(d0 * d0 * NEG_I2DLT2);
            const float dpi = th - PI_F;
            const float t1_p = (th > THR_F) ? (3.0f * wv * __expf(dpi * dpi * NEG_I2D12)) : 0.0f;
            const bool lt = pv && (th < THR_F);
            const float dh = th - HALF_PI_F;
            const float e2_p = lt ? (2.25f * __expf(dh * dh * NEG_I2DLT2)) : 0.0f;
            const unsigned ltm = __ballot_sync(FULLMASK, lt);

            if (o < 16) {
                s_acc += s_p; g_acc += g_p; t1_acc += t1_p;
                const int q = (lane - o) & 31;
                e2s += e2_p + __shfl_sync(FULLMASK, e2_p, q);
                row_lt += (int)((ltm >> lane) & 1u) + (int)((ltm >> q) & 1u);
            } else {
                s_acc  = fmaf(0.5f, s_p,  s_acc);
                g_acc  = fmaf(0.5f, g_p,  g_acc);
                t1_acc = fmaf(0.5f, t1_p, t1_acc);
                e2s += e2_p;
                row_lt += (int)((ltm >> lane) & 1u);
            }
        }
        S = 2.0f * s_acc;
        G = 2.0f * g_acc;
        O = fmaf(e2s, (float)(row_lt - 1), 2.0f * t1_acc);
    }

    #pragma unroll
    for (int off = 16; off > 0; off >>= 1) {
        S += __shfl_xor_sync(FULLMASK, S, off);
        G += __shfl_xor_sync(FULLMASK, G, off);
        O += __shfl_xor_sync(FULLMASK, O, off);
    }

    if (lane == 0) {
        const float n   = (float)__popc(mm);
        const float nn1 = n * (n - 1.0f);
        out[warp_global]         = 1.0f - 3.0f * S / nn1;
        out[C + warp_global]     = G / nn1;
        out[2 * C + warp_global] = O / (n * (3.0f + (n - 2.0f) * (n - 3.0f)));
    }
}

extern "C" void kernel_launch(void* const* d_in, const int* in_sizes, int n_in,
                              void* d_out, int out_size) {
    const float* vecs = (const float*)d_in[0];
    const int*   mask = (const int*)d_in[1];
    float* out = (float*)d_out;
    const int C = in_sizes[0] / (32 * 3);

    const int warps_per_block = 8;   // 256 threads
    const int blocks = (C + warps_per_block - 1) / warps_per_block;
    order_param_kernel<<<blocks, 256>>>(vecs, mask, out, C);
}

// round 10
// speedup vs baseline: 1.1509x; 1.0655x over previous
#include <cuda_runtime.h>
#include <cstdint>

// OrderParameter: C=30000 centrals, K=32 neighbors. One warp per central.
// R10: R9 scalar+LDS-broadcast structure, acos poly cut to degree 3
// (A&S 4.4.45, |err| <= 6.7e-5 rad; gaussian-arg sensitivity analysis gives
// ~1e-5 output impact vs 1e-3 threshold).
//
//   q_tet   = 1 - 3*S/(n(n-1)),  S via sum c^2 + 2/3 sum c + 31/9 per lane
//   q_tetra = G/(n(n-1))
//   q_oct   = [2*T1 + sum_rows e2s_j*(row_lt_j-1)] / (n*(3+(n-2)(n-3)))
//
// row_lt/e2s packed per row: val = 2.25*e2 + 256 (lt) or 0 (gt); v <= 8006,
// cnt = floor(v/256 + 0.03) exact.

#define FULLMASK 0xffffffffu

__device__ __forceinline__ float ex2f(float x) {
    float r; asm("ex2.approx.f32 %0, %1;" : "=f"(r) : "f"(x)); return r;
}
__device__ __forceinline__ float sqrt_ap(float x) {
    float r; asm("sqrt.approx.f32 %0, %1;" : "=f"(r) : "f"(x)); return r;
}

// ---- constants ----
#define PI_F      3.14159265358979323846f
#define HALF_PI_F 1.57079632679489661923f
#define THETA0_F  1.91061193216957395f     // 109.47 deg
#define PMT0_F    1.23098072142021928f     // pi - theta0
#define THR_F     2.79252680319092716f     // 160 deg
#define COS_THR_F (-0.93969262078590838f)  // cos(160 deg)
#define LOG2E_F   1.44269504088896340f
#define D_LT_F    0.17453292519943295f     // 10 deg
#define D1_F      0.20943951023931953f     // 12 deg
#define KG_F  (-LOG2E_F / (2.0f * D_LT_F * D_LT_F))   // 10-deg widths
#define K1_F  (-LOG2E_F / (2.0f * D1_F  * D1_F ))     // term1 (12 deg)

// acos(|c|), A&S 4.4.45 degree-3: |err| <= 6.7e-5 rad on [0,1]
__device__ __forceinline__ float acos_abs(float c) {
    const float t = fabsf(c);
    float p = fmaf(-0.0187293f, t, 0.0742610f);
    p = fmaf(p, t, -0.2121144f);
    p = fmaf(p, t,  1.5707288f);
    return sqrt_ap(__saturatef(1.0f - t)) * p;   // FADD.SAT folds the clamp
}

__global__ __launch_bounds__(256) void order_param_kernel(
    const float* __restrict__ vecs,  // [C, 32, 3]
    const int*   __restrict__ mask,  // [C, 32] int32 0/1
    float* __restrict__ out,         // [3, C]
    int C)
{
    __shared__ float4 sv[8][64];     // per-warp normalized vectors, duplicated

    const int tid  = threadIdx.x;
    const int w    = tid >> 5;
    const int lane = tid & 31;
    const int warp_global = blockIdx.x * 8 + w;
    if (warp_global >= C) return;

    const float* vp = vecs + (size_t)warp_global * 96 + lane * 3;
    const bool valid = mask[(size_t)warp_global * 32 + lane] != 0;
    float x = 0.0f, y = 0.0f, z = 1.0f;
    if (valid) { x = vp[0]; y = vp[1]; z = vp[2]; }
    const float inv = rsqrtf(fmaf(x, x, fmaf(y, y, z * z)));
    x *= inv; y *= inv; z *= inv;

    const unsigned mm = __ballot_sync(FULLMASK, valid);

    float S, G, O;

    if (mm == FULLMASK) {
        // ---------- fast path: all 32 neighbors valid ----------
        const float4 me = make_float4(x, y, z, 0.0f);
        sv[w][lane]      = me;
        sv[w][lane + 32] = me;
        __syncwarp();

        const float4* __restrict__ base = &sv[w][lane];

        float a2 = 0.0f, a1 = 0.0f;          // sum c^2, sum c (unordered, o16 half)
        float g = 0.0f, t1 = 0.0f;           // tetra gauss, term1 (unordered)
        float vo = 0.0f, vm = 0.0f;          // own/mirror row packed vals

        #pragma unroll
        for (int o = 1; o <= 15; o++) {
            const float4 pv = base[o];       // LDS.128, immediate offset
            const float c = fmaf(x, pv.x, fmaf(y, pv.y, z * pv.z));
            a2 = fmaf(c, c, a2);
            a1 += c;

            const float r = acos_abs(c);     // acos(|c|)
            const bool gt = c < COS_THR_F;   // theta > 160 deg
            const float ctr = gt ? 0.0f : ((c >= 0.0f) ? THETA0_F : PMT0_F);
            const float kk  = gt ? K1_F : KG_F;
            const float d1  = r - ctr;
            const float e1  = ex2f((kk * d1) * d1);
            g  += gt ? 0.0f : e1;
            t1  = fmaf(gt ? 3.0f : 0.0f, e1, t1);

            const float d2 = r - HALF_PI_F;
            const float e2 = ex2f((KG_F * d2) * d2);
            const float val = gt ? 0.0f : fmaf(2.25f, e2, 256.0f);
            vo += val;
            vm += __shfl_sync(FULLMASK, val, lane + (32 - o));  // mirror row
        }
        {   // o = 16: pair computed by both endpoints -> half-weight symmetric,
            // own-only row accumulation (ordered (j, j+16) once)
            const float4 pv = base[16];
            const float c = fmaf(x, pv.x, fmaf(y, pv.y, z * pv.z));
            a2 = fmaf(0.5f * c, c, a2);
            a1 = fmaf(0.5f, c, a1);

            const float r = acos_abs(c);
            const bool gt = c < COS_THR_F;
            const float ctr = gt ? 0.0f : ((c >= 0.0f) ? THETA0_F : PMT0_F);
            const float kk  = gt ? K1_F : KG_F;
            const float d1  = r - ctr;
            const float e1  = ex2f((kk * d1) * d1);
            g  = fmaf(gt ? 0.0f : 0.5f, e1, g);
            t1 = fmaf(gt ? 1.5f : 0.0f, e1, t1);

            const float d2 = r - HALF_PI_F;
            const float e2 = ex2f((KG_F * d2) * d2);
            const float val = gt ? 0.0f : fmaf(2.25f, e2, 256.0f);
            vo += val;
        }

        // per-lane partials; identities hold after the warp reduction
        S = 2.0f * fmaf(2.0f / 3.0f, a1, a2) + 31.0f / 9.0f;
        G = 2.0f * g;
        const float v   = vo + vm;                      // e2s + 256*row_lt
        const float cnt = floorf(fmaf(v, 1.0f / 256.0f, 0.03f));
        const float e2s = fmaf(-256.0f, cnt, v);
        O = fmaf(e2s, cnt - 1.0f, 2.0f * t1);
    } else {
        // ---------- generic path (verified R3 loop) ----------
        const float NEG_I2DLT2 = -1.0f / (2.0f * D_LT_F * D_LT_F);
        const float NEG_I2D12  = -1.0f / (2.0f * D1_F * D1_F);

        float s_acc = 0.0f, g_acc = 0.0f, t1_acc = 0.0f, e2s = 0.0f;
        int row_lt = 0;
        #pragma unroll
        for (int o = 1; o <= 16; o++) {
            const int p = (lane + o) & 31;
            const float vx = __shfl_sync(FULLMASK, x, p);
            const float vy = __shfl_sync(FULLMASK, y, p);
            const float vz = __shfl_sync(FULLMASK, z, p);
            const bool pv = valid && ((mm >> p) & 1u);
            const float wv = pv ? 1.0f : 0.0f;

            float c = fmaf(x, vx, fmaf(y, vy, z * vz));
            c = fminf(1.0f, fmaxf(-1.0f, c));
            const float th = acosf(c);

            const float a = c + (1.0f / 3.0f);
            const float s_p = wv * a * a;
            const float d0 = th - THETA0_F;
            const float g_p = wv * __expf(d0 * d0 * NEG_I2DLT2);
            const float dpi = th - PI_F;
            const float t1_p = (th > THR_F) ? (3.0f * wv * __expf(dpi * dpi * NEG_I2D12)) : 0.0f;
            const bool lt = pv && (th < THR_F);
            const float dh = th - HALF_PI_F;
            const float e2_p = lt ? (2.25f * __expf(dh * dh * NEG_I2DLT2)) : 0.0f;
            const unsigned ltm = __ballot_sync(FULLMASK, lt);

            if (o < 16) {
                s_acc += s_p; g_acc += g_p; t1_acc += t1_p;
                const int q = (lane - o) & 31;
                e2s += e2_p + __shfl_sync(FULLMASK, e2_p, q);
                row_lt += (int)((ltm >> lane) & 1u) + (int)((ltm >> q) & 1u);
            } else {
                s_acc  = fmaf(0.5f, s_p,  s_acc);
                g_acc  = fmaf(0.5f, g_p,  g_acc);
                t1_acc = fmaf(0.5f, t1_p, t1_acc);
                e2s += e2_p;
                row_lt += (int)((ltm >> lane) & 1u);
            }
        }
        S = 2.0f * s_acc;
        G = 2.0f * g_acc;
        O = fmaf(e2s, (float)(row_lt - 1), 2.0f * t1_acc);
    }

    #pragma unroll
    for (int off = 16; off > 0; off >>= 1) {
        S += __shfl_xor_sync(FULLMASK, S, off);
        G += __shfl_xor_sync(FULLMASK, G, off);
        O += __shfl_xor_sync(FULLMASK, O, off);
    }

    if (lane == 0) {
        const float n   = (float)__popc(mm);
        const float nn1 = n * (n - 1.0f);
        out[warp_global]         = 1.0f - 3.0f * S / nn1;
        out[C + warp_global]     = G / nn1;
        out[2 * C + warp_global] = O / (n * (3.0f + (n - 2.0f) * (n - 3.0f)));
    }
}

extern "C" void kernel_launch(void* const* d_in, const int* in_sizes, int n_in,
                              void* d_out, int out_size) {
    const float* vecs = (const float*)d_in[0];
    const int*   mask = (const int*)d_in[1];
    float* out = (float*)d_out;
    const int C = in_sizes[0] / (32 * 3);

    const int warps_per_block = 8;   // 256 threads
    const int blocks = (C + warps_per_block - 1) / warps_per_block;
    order_param_kernel<<<blocks, 256>>>(vecs, mask, out, C);
}